// round 12
// baseline (speedup 1.0000x reference)
#include <cuda_runtime.h>
#include <cuda_fp16.h>
#include <cstdint>

#define BATCH 256

// ---------------- scratch ----------------
__device__ unsigned char g_m3[BATCH * 1024];
__device__ unsigned char g_m4[BATCH * 256];
__device__ __align__(16) __half g_p1hi[BATCH * 34 * 34 * 32];
__device__ __align__(16) __half g_p2h[BATCH * 16384];
__device__ __align__(16) __half g_p2l[BATCH * 16384];
__device__ __align__(16) __half g_wf1h[128 * 16384];
__device__ __align__(16) unsigned char g_w2p[46080];   // conv2 smem-layout W image
__device__ float g_h[BATCH * 128];

// ---------------- helpers ----------------
static __device__ __forceinline__ uint32_t s2u(const void* p) {
    uint32_t a;
    asm("{ .reg .u64 t; cvta.to.shared.u64 t, %1; cvt.u32.u64 %0, t; }" : "=r"(a) : "l"(p));
    return a;
}
#define LDSM4(r, addr) \
    asm volatile("ldmatrix.sync.aligned.m8n8.x4.shared.b16 {%0,%1,%2,%3}, [%4];" \
        : "=r"((r)[0]), "=r"((r)[1]), "=r"((r)[2]), "=r"((r)[3]) : "r"(addr))
#define MMA16816F(c, a, b0, b1) \
    asm volatile("mma.sync.aligned.m16n8k16.row.col.f32.f16.f16.f32 " \
        "{%0,%1,%2,%3}, {%4,%5,%6,%7}, {%8,%9}, {%0,%1,%2,%3};" \
        : "+f"((c)[0]), "+f"((c)[1]), "+f"((c)[2]), "+f"((c)[3]) \
        : "r"((a)[0]), "r"((a)[1]), "r"((a)[2]), "r"((a)[3]), "r"(b0), "r"(b1))

static __device__ __forceinline__ uint64_t pack2(float lo, float hi) {
    uint64_t d;
    asm("mov.b64 %0, {%1, %2};" : "=l"(d) : "f"(lo), "f"(hi));
    return d;
}
static __device__ __forceinline__ void fma2(uint64_t& d, uint64_t a, uint64_t b) {
    asm("fma.rn.f32x2 %0, %1, %2, %0;" : "+l"(d) : "l"(a), "l"(b));
}
static __device__ __forceinline__ void unpack2(uint64_t v, float& lo, float& hi) {
    asm("mov.b64 {%0, %1}, %2;" : "=f"(lo), "=f"(hi) : "l"(v));
}

// ---------------- conv1 fused: w-preps + masks + conv + pool + border + h-init ----------------
#define C1_XS    0        // 64*65*4 = 16640
#define C1_W1D   16640    // 288 float2 = 2304
#define C1_B1    18944    // 128
#define C1_CS    19072    // 4096
#define C1_M1    23168    // 4096
#define C1_M2    27264    // 1024
#define C1_M3    28288    // 1024
#define C1_M4    29312    // 256
#define C1_HBUF  29568    // 512*17*4 = 34816
#define C1_SMEM  64384

__global__ void __launch_bounds__(256, 2) conv1_kernel(const float* __restrict__ x,
                                                       const int* __restrict__ cmap,
                                                       const float* __restrict__ W1,
                                                       const float* __restrict__ b1,
                                                       const float* __restrict__ bfc1,
                                                       const float* __restrict__ Wfc1,
                                                       const float* __restrict__ W2) {
    extern __shared__ char sm1[];
    float* xs = (float*)(sm1 + C1_XS);                 // pitch 65
    float2* W1d = (float2*)(sm1 + C1_W1D);
    float* b1s = (float*)(sm1 + C1_B1);
    unsigned char* cs  = (unsigned char*)(sm1 + C1_CS);
    unsigned char* m1s = (unsigned char*)(sm1 + C1_M1);
    unsigned char* m2s = (unsigned char*)(sm1 + C1_M2);
    unsigned char* m3s = (unsigned char*)(sm1 + C1_M3);
    unsigned char* m4s = (unsigned char*)(sm1 + C1_M4);
    uint32_t* hbuf = (uint32_t*)(sm1 + C1_HBUF);       // [512][17]
    int b = blockIdx.x, t = threadIdx.x;

    // distributed Wfc1 -> fp16 hi (8192 floats per CTA)
    {
        const float4* src = (const float4*)Wfc1 + (size_t)b * 2048;
        __half2* dst = (__half2*)(g_wf1h + (size_t)b * 8192);
        for (int i = t; i < 2048; i += 256) {
            float4 v = src[i];
            __half2 h0, h1;
            h0.x = __float2half_rn(v.x); h0.y = __float2half_rn(v.y);
            h1.x = __float2half_rn(v.z); h1.y = __float2half_rn(v.w);
            dst[i * 2] = h0;
            dst[i * 2 + 1] = h1;
        }
    }
    // distributed W2 -> conv2 smem-layout image (72 weights per CTA)
    if (t < 72) {
        int i = b * 72 + t;
        int oc = i / 288, rem = i - oc * 288, ic = rem / 9, tap = rem - ic * 9;
        *(__half*)(g_w2p + tap * 5120 + oc * 80 + ic * 2) = __float2half_rn(W2[i]);
    }

    const float* xb = x + b * 4096;
    const int* cb = cmap + b * 4096;
    for (int i = t; i < 4096; i += 256) {
        xs[(i >> 6) * 65 + (i & 63)] = xb[i];
        cs[i] = (unsigned char)cb[i];
    }
    for (int i = t; i < 288; i += 256) { float w = W1[i]; W1d[i] = make_float2(w, w); }
    if (t < 32) b1s[t] = b1[t];
    if (t < 128) g_h[b * 128 + t] = bfc1[t];
    __syncthreads();

    for (int p = t; p < 4096; p += 256) {
        int i = p >> 6, j = p & 63;
        int s = 0;
        for (int di = 0; di < 3; di++) {
            int ii = i + di; if (ii >= 64) break;
            for (int dj = 0; dj < 3; dj++) {
                int jj = j + dj; if (jj >= 64) break;
                s += cs[(ii << 6) | jj];
            }
        }
        m1s[p] = (s > 1);
    }
    __syncthreads();
    for (int p = t; p < 1024; p += 256) {
        int i = p >> 5, j = p & 31;
        int s = m1s[((2 * i) << 6) | (2 * j)] + m1s[((2 * i) << 6) | (2 * j + 1)]
              + m1s[((2 * i + 1) << 6) | (2 * j)] + m1s[((2 * i + 1) << 6) | (2 * j + 1)];
        m2s[p] = (s > 1);
    }
    __syncthreads();
    for (int p = t; p < 1024; p += 256) {
        int i = p >> 5, j = p & 31;
        int s = 0;
        for (int di = 0; di < 3; di++) {
            int ii = i + di; if (ii >= 32) break;
            for (int dj = 0; dj < 3; dj++) {
                int jj = j + dj; if (jj >= 32) break;
                s += m2s[(ii << 5) | jj];
            }
        }
        m3s[p] = (s > 1);
    }
    __syncthreads();
    for (int p = t; p < 1024; p += 256) g_m3[b * 1024 + p] = m3s[p];
    if (t < 256) {
        int i = t >> 4, j = t & 15;
        int s = m3s[((2 * i) << 5) | (2 * j)] + m3s[((2 * i) << 5) | (2 * j + 1)]
              + m3s[((2 * i + 1) << 5) | (2 * j)] + m3s[((2 * i + 1) << 5) | (2 * j + 1)];
        m4s[t] = (s > 1);
        g_m4[b * 256 + t] = m4s[t];
    }

    // p1 border zero
    {
        const uint4 z = {0u, 0u, 0u, 0u};
        for (int i = t; i < 528; i += 256) {
            int q = i & 3, cl = i >> 2;
            int row, col;
            if (cl < 34)       { row = 0;        col = cl; }
            else if (cl < 68)  { row = 33;       col = cl - 34; }
            else if (cl < 100) { row = cl - 67;  col = 0; }
            else               { row = cl - 99;  col = 33; }
            ((uint4*)g_p1hi)[((size_t)(b * 34 + row) * 34 + col) * 4 + q] = z;
        }
    }

    uint32_t* ghi = (uint32_t*)g_p1hi;

    for (int half = 0; half < 2; half++) {
        #pragma unroll
        for (int pp = 0; pp < 2; pp++) {
            int lp = pp * 256 + t;
            int p  = half * 512 + lp;
            int oi = p >> 5, oj = p & 31;
            if (!m2s[p]) {
                #pragma unroll
                for (int k = 0; k < 16; k++) hbuf[lp * 17 + k] = 0u;
                continue;
            }
            float xv[4][4];
            int r0 = 2 * oi - 1, c0 = 2 * oj - 1;
            #pragma unroll
            for (int a = 0; a < 4; a++) {
                int r = r0 + a;
                #pragma unroll
                for (int c = 0; c < 4; c++) {
                    int cc = c0 + c;
                    xv[a][c] = (r >= 0 && r < 64 && cc >= 0 && cc < 64) ? xs[r * 65 + cc] : 0.f;
                }
            }
            uint64_t pk[4][3];
            #pragma unroll
            for (int r = 0; r < 4; r++)
                #pragma unroll
                for (int dj = 0; dj < 3; dj++)
                    pk[r][dj] = pack2(xv[r][dj], xv[r][dj + 1]);
            float mm00 = m1s[((2 * oi) << 6) | (2 * oj)]     ? 1.f : 0.f;
            float mm01 = m1s[((2 * oi) << 6) | (2 * oj + 1)] ? 1.f : 0.f;
            float mm10 = m1s[((2 * oi + 1) << 6) | (2 * oj)] ? 1.f : 0.f;
            float mm11 = m1s[((2 * oi + 1) << 6) | (2 * oj + 1)] ? 1.f : 0.f;
            uint32_t hw = 0;
            for (int oc = 0; oc < 32; oc++) {
                float bb = b1s[oc];
                uint64_t accA = pack2(bb, bb);
                uint64_t accB = accA;
                #pragma unroll
                for (int tap = 0; tap < 9; tap++) {
                    const int di = tap / 3, dj = tap - 3 * di;
                    uint64_t w2 = *(const uint64_t*)&W1d[oc * 9 + tap];
                    fma2(accA, pk[di][dj], w2);
                    fma2(accB, pk[di + 1][dj], w2);
                }
                float a00, a01, a10, a11;
                unpack2(accA, a00, a01);
                unpack2(accB, a10, a11);
                float v = fmaxf(fmaxf(mm00 * fmaxf(a00, 0.f), mm01 * fmaxf(a01, 0.f)),
                                fmaxf(mm10 * fmaxf(a10, 0.f), mm11 * fmaxf(a11, 0.f)));
                uint32_t hu = (uint32_t)__half_as_ushort(__float2half_rn(v));
                if (oc & 1) {
                    hw |= hu << 16;
                    hbuf[lp * 17 + (oc >> 1)] = hw;
                } else hw = hu;
            }
        }
        __syncthreads();
        for (int i = t; i < 8192; i += 256) {
            int px = i >> 4, w = i & 15;
            int oi = half * 16 + (px >> 5), oj = px & 31;
            ghi[((size_t)(b * 34 + oi + 1) * 34 + oj + 1) * 16 + w] = hbuf[px * 17 + w];
        }
        __syncthreads();
    }
}

// ---------------- conv2 via mma.sync fp16 (A hi-only, 256 thr, 3 CTAs/SM) ----------------
#define SM_W     0        // 46080
#define SM_STRIP 46080    // 27200
#define SM_B2    73280    // 256
#define SM_M3    73536    // 1024
#define SM_M4    74560    // 256
#define C2_SMEM  74816

__global__ void __launch_bounds__(256, 3) conv2_mma_kernel(const float* __restrict__ b2) {
    extern __shared__ char sm[];
    float* b2s = (float*)(sm + SM_B2);
    int t = threadIdx.x;
    int b = blockIdx.x >> 1, hf = blockIdx.x & 1;
    int warp = t >> 5, lane = t & 31;
    uint32_t sb = s2u(sm);

    for (int i = t; i < 2880; i += 256)
        *(uint4*)(sm + SM_W + i * 16) = *(const uint4*)(g_w2p + i * 16);
    if (t < 64) b2s[t] = b2[t];
    for (int i = t; i < 1024; i += 256) sm[SM_M3 + i] = (char)g_m3[b * 1024 + i];
    sm[SM_M4 + t] = (char)g_m4[b * 256 + t];

    int wm = warp & 3, wn = warp >> 2;   // 4 M x 2 N(32oc)
    int oc0 = wn * 32;
    int g = lane >> 2, qu = lane & 3;
    int rowlane = lane & 15;
    int aKoff = (lane >= 16) ? 16 : 0;
    int grpB = lane >> 3;
    int ocoffB = ((grpB >> 1) << 3) + (lane & 7);
    int bKoff = (grpB & 1) * 16;

    for (int it = 0; it < 2; it++) {
        int mt = hf * 2 + it;
        __syncthreads();
        const uint4* shp = (const uint4*)g_p1hi + ((size_t)(b * 34 + 8 * mt) * 34) * 4;
        for (int j = t; j < 1360; j += 256) {
            uint4 v = shp[j];
            int px = j >> 2, q = j & 3;
            *(uint4*)(sm + SM_STRIP + px * 80 + q * 16) = v;
        }
        __syncthreads();

        float acc[4][4][4];
        #pragma unroll
        for (int mi = 0; mi < 4; mi++)
            #pragma unroll
            for (int nt = 0; nt < 4; nt++)
                #pragma unroll
                for (int e = 0; e < 4; e++) acc[mi][nt][e] = 0.f;

        #pragma unroll
        for (int tap = 0; tap < 9; tap++) {
            const int di = tap / 3, dj = tap - di * 3;
            #pragma unroll
            for (int kc = 0; kc < 2; kc++) {
                uint32_t ah[4][4];
                #pragma unroll
                for (int mi = 0; mi < 4; mi++) {
                    int lr = 2 * wm + (mi >> 1);
                    int c0 = (mi & 1) * 16;
                    uint32_t addr = sb + SM_STRIP +
                        (uint32_t)(((lr + di) * 34 + c0 + rowlane + dj) * 80 + kc * 32 + aKoff);
                    LDSM4(ah[mi], addr);
                }
                #pragma unroll
                for (int nb = 0; nb < 2; nb++) {
                    uint32_t bh[4];
                    uint32_t baddr = sb + SM_W +
                        (uint32_t)(tap * 5120 + (oc0 + nb * 16 + ocoffB) * 80 + kc * 32 + bKoff);
                    LDSM4(bh, baddr);
                    #pragma unroll
                    for (int mi = 0; mi < 4; mi++)
                        #pragma unroll
                        for (int s2 = 0; s2 < 2; s2++) {
                            int nt = nb * 2 + s2;
                            MMA16816F(acc[mi][nt], ah[mi], bh[s2 * 2], bh[s2 * 2 + 1]);
                        }
                }
            }
        }

        int mtrow = mt * 8;
        int prg = mt * 4 + wm;
        #pragma unroll
        for (int mi = 0; mi < 2; mi++)
            #pragma unroll
            for (int nt = 0; nt < 4; nt++)
                #pragma unroll
                for (int e = 0; e < 4; e++) {
                    int col = mi * 16 + g + ((e >> 1) ? 8 : 0);
                    int occ = oc0 + nt * 8 + qu * 2 + (e & 1);
                    float bb = b2s[occ];
                    float v0 = sm[SM_M3 + (mtrow + 2 * wm) * 32 + col]
                               ? fmaxf(acc[mi][nt][e] + bb, 0.f) : 0.f;
                    float v1 = sm[SM_M3 + (mtrow + 2 * wm + 1) * 32 + col]
                               ? fmaxf(acc[mi + 2][nt][e] + bb, 0.f) : 0.f;
                    float v = fmaxf(v0, v1);
                    float vp = __shfl_xor_sync(0xffffffffu, v, 4);
                    if (!(g & 1)) {
                        float pooled = fmaxf(v, vp);
                        int pc = col >> 1;
                        if (!sm[SM_M4 + prg * 16 + pc]) pooled = 0.f;
                        __half hb = __float2half_rn(pooled);
                        __half lb = __float2half_rn(pooled - __half2float(hb));
                        size_t o = (size_t)b * 16384 + occ * 256 + prg * 16 + pc;
                        g_p2h[o] = hb;
                        g_p2l[o] = lb;
                    }
                }
    }
}

// ---------------- FC1 via mma.sync fp16 (2-term: Ah*Wh + Al*Wh) ----------------
// smem: Ah 18432 | Al 18432 | Wh 18432 = 55296 (pitch 144B)
#define F1_AH 0
#define F1_AL 18432
#define F1_WH 36864
#define F1_SMEM 55296

// grid (2 M-tiles of 128, 128 k-chunks of 128), 256 threads
__global__ void __launch_bounds__(256, 2) fc1_mma_kernel() {
    extern __shared__ char sm[];
    int t = threadIdx.x;
    int mtile = blockIdx.x, kc = blockIdx.y;
    int warp = t >> 5, lane = t & 31;
    uint32_t sb = s2u(sm);
    int wm = warp & 3, wn = warp >> 2;   // 4 M(32px) x 2 N(64oc)
    int g = lane >> 2, qu = lane & 3;
    int rowlane = lane & 15;
    int aKoff = (lane >= 16) ? 16 : 0;
    int grpB = lane >> 3;
    int ocoffB = ((grpB >> 1) << 3) + (lane & 7);
    int bKoff = (grpB & 1) * 16;

    float acc[2][8][4];
    #pragma unroll
    for (int mi = 0; mi < 2; mi++)
        #pragma unroll
        for (int nt = 0; nt < 8; nt++)
            #pragma unroll
            for (int e = 0; e < 4; e++) acc[mi][nt][e] = 0.f;

    const uint32_t* Ahg = (const uint32_t*)g_p2h;
    const uint32_t* Alg = (const uint32_t*)g_p2l;
    const uint32_t* Whg = (const uint32_t*)g_wf1h;

    for (int sub = 0; sub < 2; sub++) {
        int k0 = kc * 128 + sub * 64;
        __syncthreads();
        for (int i = t; i < 4096; i += 256) {
            int row = i >> 5, w = i & 31;
            size_t gi = (size_t)(mtile * 128 + row) * 8192 + (k0 >> 1) + w;
            *(uint32_t*)(sm + F1_AH + row * 144 + w * 4) = Ahg[gi];
            *(uint32_t*)(sm + F1_AL + row * 144 + w * 4) = Alg[gi];
            size_t wi = (size_t)row * 8192 + (k0 >> 1) + w;   // row == oc (128)
            *(uint32_t*)(sm + F1_WH + row * 144 + w * 4) = Whg[wi];
        }
        __syncthreads();
        #pragma unroll
        for (int k16 = 0; k16 < 4; k16++) {
            uint32_t ah[2][4], al[2][4];
            #pragma unroll
            for (int mi = 0; mi < 2; mi++) {
                int row = wm * 32 + mi * 16 + rowlane;
                uint32_t addr = sb + F1_AH + (uint32_t)(row * 144 + k16 * 32 + aKoff);
                LDSM4(ah[mi], addr);
                LDSM4(al[mi], addr + 18432);
            }
            #pragma unroll
            for (int nb = 0; nb < 4; nb++) {
                uint32_t bh[4];
                int oc0 = wn * 64 + nb * 16;
                uint32_t baddr = sb + F1_WH + (uint32_t)((oc0 + ocoffB) * 144 + k16 * 32 + bKoff);
                LDSM4(bh, baddr);
                #pragma unroll
                for (int mi = 0; mi < 2; mi++)
                    #pragma unroll
                    for (int s2 = 0; s2 < 2; s2++) {
                        int nt = nb * 2 + s2;
                        MMA16816F(acc[mi][nt], ah[mi], bh[s2 * 2], bh[s2 * 2 + 1]);
                        MMA16816F(acc[mi][nt], al[mi], bh[s2 * 2], bh[s2 * 2 + 1]);
                    }
            }
        }
    }
    #pragma unroll
    for (int mi = 0; mi < 2; mi++)
        #pragma unroll
        for (int nt = 0; nt < 8; nt++)
            #pragma unroll
            for (int e = 0; e < 4; e++) {
                int row = mtile * 128 + wm * 32 + mi * 16 + g + ((e >> 1) ? 8 : 0);
                int col = wn * 64 + nt * 8 + qu * 2 + (e & 1);
                atomicAdd(&g_h[row * 128 + col], acc[mi][nt][e]);
            }
}

// ---------------- FC2 warp-parallel ----------------
__global__ void __launch_bounds__(320) fc2_kernel(const float* __restrict__ Wfc2,
                                                  const float* __restrict__ bfc2,
                                                  float* __restrict__ out) {
    int b = blockIdx.x;
    int w = threadIdx.x >> 5, lane = threadIdx.x & 31;
    float s = 0.f;
    const float* wp = Wfc2 + w * 128;
    const float* hp = g_h + b * 128;
    #pragma unroll
    for (int k = lane; k < 128; k += 32)
        s += fmaxf(hp[k], 0.f) * wp[k];
    #pragma unroll
    for (int o = 16; o; o >>= 1) s += __shfl_xor_sync(0xffffffffu, s, o);
    if (lane == 0) out[b * 10 + w] = s + bfc2[w];
}

// ---------------- launch ----------------
extern "C" void kernel_launch(void* const* d_in, const int* in_sizes, int n_in,
                              void* d_out, int out_size) {
    const float* x    = (const float*)d_in[0];
    const int*   cmap = (const int*)  d_in[1];
    const float* W1   = (const float*)d_in[2];
    const float* b1   = (const float*)d_in[3];
    const float* W2   = (const float*)d_in[4];
    const float* b2   = (const float*)d_in[5];
    const float* Wfc1 = (const float*)d_in[6];
    const float* bfc1 = (const float*)d_in[7];
    const float* Wfc2 = (const float*)d_in[8];
    const float* bfc2 = (const float*)d_in[9];
    float* out = (float*)d_out;

    cudaFuncSetAttribute(conv1_kernel, cudaFuncAttributeMaxDynamicSharedMemorySize, C1_SMEM);
    cudaFuncSetAttribute(conv2_mma_kernel, cudaFuncAttributeMaxDynamicSharedMemorySize, C2_SMEM);
    cudaFuncSetAttribute(fc1_mma_kernel, cudaFuncAttributeMaxDynamicSharedMemorySize, F1_SMEM);

    conv1_kernel<<<BATCH, 256, C1_SMEM>>>(x, cmap, W1, b1, bfc1, Wfc1, W2);
    conv2_mma_kernel<<<BATCH * 2, 256, C2_SMEM>>>(b2);
    dim3 g1(2, 128);
    fc1_mma_kernel<<<g1, 256, F1_SMEM>>>();
    fc2_kernel<<<BATCH, 320>>>(Wfc2, bfc2, out);
}

// round 14
// speedup vs baseline: 1.9460x; 1.9460x over previous
#include <cuda_runtime.h>
#include <cuda_fp16.h>
#include <cstdint>

#define BATCH 256

// ---------------- scratch ----------------
__device__ unsigned char g_m3[BATCH * 1024];
__device__ unsigned char g_m4[BATCH * 256];
__device__ __align__(16) __half g_p1hi[BATCH * 34 * 34 * 32];
__device__ __align__(16) __half g_p2h[BATCH * 16384];
__device__ __align__(16) __half g_p2l[BATCH * 16384];
__device__ __align__(16) __half g_wf1h[128 * 16384];
__device__ __align__(16) unsigned char g_w2p[46080];   // conv2 smem-layout W image
__device__ float g_h[BATCH * 128];

// ---------------- helpers ----------------
static __device__ __forceinline__ uint32_t s2u(const void* p) {
    uint32_t a;
    asm("{ .reg .u64 t; cvta.to.shared.u64 t, %1; cvt.u32.u64 %0, t; }" : "=r"(a) : "l"(p));
    return a;
}
#define LDSM4(r, addr) \
    asm volatile("ldmatrix.sync.aligned.m8n8.x4.shared.b16 {%0,%1,%2,%3}, [%4];" \
        : "=r"((r)[0]), "=r"((r)[1]), "=r"((r)[2]), "=r"((r)[3]) : "r"(addr))
#define MMA16816F(c, a, b0, b1) \
    asm volatile("mma.sync.aligned.m16n8k16.row.col.f32.f16.f16.f32 " \
        "{%0,%1,%2,%3}, {%4,%5,%6,%7}, {%8,%9}, {%0,%1,%2,%3};" \
        : "+f"((c)[0]), "+f"((c)[1]), "+f"((c)[2]), "+f"((c)[3]) \
        : "r"((a)[0]), "r"((a)[1]), "r"((a)[2]), "r"((a)[3]), "r"(b0), "r"(b1))

static __device__ __forceinline__ uint64_t pack2(float lo, float hi) {
    uint64_t d;
    asm("mov.b64 %0, {%1, %2};" : "=l"(d) : "f"(lo), "f"(hi));
    return d;
}
static __device__ __forceinline__ void fma2(uint64_t& d, uint64_t a, uint64_t b) {
    asm("fma.rn.f32x2 %0, %1, %2, %0;" : "+l"(d) : "l"(a), "l"(b));
}
static __device__ __forceinline__ void unpack2(uint64_t v, float& lo, float& hi) {
    asm("mov.b64 {%0, %1}, %2;" : "=f"(lo), "=f"(hi) : "l"(v));
}

// ---------------- conv1 fused: w-preps + masks + conv + pool + border + h-init ----------------
#define C1_XS    0        // 64*65*4 = 16640
#define C1_W1D   16640    // 288 float2 = 2304
#define C1_B1    18944    // 128
#define C1_CS    19072    // 4096
#define C1_M1    23168    // 4096
#define C1_M2    27264    // 1024
#define C1_M3    28288    // 1024
#define C1_M4    29312    // 256
#define C1_HBUF  29568    // 512*17*4 = 34816
#define C1_SMEM  64384

__global__ void __launch_bounds__(256, 2) conv1_kernel(const float* __restrict__ x,
                                                       const int* __restrict__ cmap,
                                                       const float* __restrict__ W1,
                                                       const float* __restrict__ b1,
                                                       const float* __restrict__ bfc1,
                                                       const float* __restrict__ Wfc1,
                                                       const float* __restrict__ W2) {
    extern __shared__ char sm1[];
    float* xs = (float*)(sm1 + C1_XS);                 // pitch 65
    float2* W1d = (float2*)(sm1 + C1_W1D);
    float* b1s = (float*)(sm1 + C1_B1);
    unsigned char* cs  = (unsigned char*)(sm1 + C1_CS);
    unsigned char* m1s = (unsigned char*)(sm1 + C1_M1);
    unsigned char* m2s = (unsigned char*)(sm1 + C1_M2);
    unsigned char* m3s = (unsigned char*)(sm1 + C1_M3);
    unsigned char* m4s = (unsigned char*)(sm1 + C1_M4);
    uint32_t* hbuf = (uint32_t*)(sm1 + C1_HBUF);       // [512][17]
    int b = blockIdx.x, t = threadIdx.x;

    // distributed Wfc1 -> fp16 hi (8192 floats per CTA)
    {
        const float4* src = (const float4*)Wfc1 + (size_t)b * 2048;
        __half2* dst = (__half2*)(g_wf1h + (size_t)b * 8192);
        for (int i = t; i < 2048; i += 256) {
            float4 v = src[i];
            __half2 h0, h1;
            h0.x = __float2half_rn(v.x); h0.y = __float2half_rn(v.y);
            h1.x = __float2half_rn(v.z); h1.y = __float2half_rn(v.w);
            dst[i * 2] = h0;
            dst[i * 2 + 1] = h1;
        }
    }
    // distributed W2 -> conv2 smem-layout image (72 weights per CTA)
    if (t < 72) {
        int i = b * 72 + t;
        int oc = i / 288, rem = i - oc * 288, ic = rem / 9, tap = rem - ic * 9;
        *(__half*)(g_w2p + tap * 5120 + oc * 80 + ic * 2) = __float2half_rn(W2[i]);
    }

    const float* xb = x + b * 4096;
    const int* cb = cmap + b * 4096;
    for (int i = t; i < 4096; i += 256) {
        xs[(i >> 6) * 65 + (i & 63)] = xb[i];
        cs[i] = (unsigned char)cb[i];
    }
    for (int i = t; i < 288; i += 256) { float w = W1[i]; W1d[i] = make_float2(w, w); }
    if (t < 32) b1s[t] = b1[t];
    if (t < 128) g_h[b * 128 + t] = bfc1[t];
    __syncthreads();

    for (int p = t; p < 4096; p += 256) {
        int i = p >> 6, j = p & 63;
        int s = 0;
        for (int di = 0; di < 3; di++) {
            int ii = i + di; if (ii >= 64) break;
            for (int dj = 0; dj < 3; dj++) {
                int jj = j + dj; if (jj >= 64) break;
                s += cs[(ii << 6) | jj];
            }
        }
        m1s[p] = (s > 1);
    }
    __syncthreads();
    for (int p = t; p < 1024; p += 256) {
        int i = p >> 5, j = p & 31;
        int s = m1s[((2 * i) << 6) | (2 * j)] + m1s[((2 * i) << 6) | (2 * j + 1)]
              + m1s[((2 * i + 1) << 6) | (2 * j)] + m1s[((2 * i + 1) << 6) | (2 * j + 1)];
        m2s[p] = (s > 1);
    }
    __syncthreads();
    for (int p = t; p < 1024; p += 256) {
        int i = p >> 5, j = p & 31;
        int s = 0;
        for (int di = 0; di < 3; di++) {
            int ii = i + di; if (ii >= 32) break;
            for (int dj = 0; dj < 3; dj++) {
                int jj = j + dj; if (jj >= 32) break;
                s += m2s[(ii << 5) | jj];
            }
        }
        m3s[p] = (s > 1);
    }
    __syncthreads();
    for (int p = t; p < 1024; p += 256) g_m3[b * 1024 + p] = m3s[p];
    if (t < 256) {
        int i = t >> 4, j = t & 15;
        int s = m3s[((2 * i) << 5) | (2 * j)] + m3s[((2 * i) << 5) | (2 * j + 1)]
              + m3s[((2 * i + 1) << 5) | (2 * j)] + m3s[((2 * i + 1) << 5) | (2 * j + 1)];
        m4s[t] = (s > 1);
        g_m4[b * 256 + t] = m4s[t];
    }

    // p1 border zero
    {
        const uint4 z = {0u, 0u, 0u, 0u};
        for (int i = t; i < 528; i += 256) {
            int q = i & 3, cl = i >> 2;
            int row, col;
            if (cl < 34)       { row = 0;        col = cl; }
            else if (cl < 68)  { row = 33;       col = cl - 34; }
            else if (cl < 100) { row = cl - 67;  col = 0; }
            else               { row = cl - 99;  col = 33; }
            ((uint4*)g_p1hi)[((size_t)(b * 34 + row) * 34 + col) * 4 + q] = z;
        }
    }

    uint32_t* ghi = (uint32_t*)g_p1hi;

    for (int half = 0; half < 2; half++) {
        #pragma unroll
        for (int pp = 0; pp < 2; pp++) {
            int lp = pp * 256 + t;
            int p  = half * 512 + lp;
            int oi = p >> 5, oj = p & 31;
            if (!m2s[p]) {
                #pragma unroll
                for (int k = 0; k < 16; k++) hbuf[lp * 17 + k] = 0u;
                continue;
            }
            float xv[4][4];
            int r0 = 2 * oi - 1, c0 = 2 * oj - 1;
            #pragma unroll
            for (int a = 0; a < 4; a++) {
                int r = r0 + a;
                #pragma unroll
                for (int c = 0; c < 4; c++) {
                    int cc = c0 + c;
                    xv[a][c] = (r >= 0 && r < 64 && cc >= 0 && cc < 64) ? xs[r * 65 + cc] : 0.f;
                }
            }
            uint64_t pk[4][3];
            #pragma unroll
            for (int r = 0; r < 4; r++)
                #pragma unroll
                for (int dj = 0; dj < 3; dj++)
                    pk[r][dj] = pack2(xv[r][dj], xv[r][dj + 1]);
            float mm00 = m1s[((2 * oi) << 6) | (2 * oj)]     ? 1.f : 0.f;
            float mm01 = m1s[((2 * oi) << 6) | (2 * oj + 1)] ? 1.f : 0.f;
            float mm10 = m1s[((2 * oi + 1) << 6) | (2 * oj)] ? 1.f : 0.f;
            float mm11 = m1s[((2 * oi + 1) << 6) | (2 * oj + 1)] ? 1.f : 0.f;
            uint32_t hw = 0;
            for (int oc = 0; oc < 32; oc++) {
                float bb = b1s[oc];
                uint64_t accA = pack2(bb, bb);
                uint64_t accB = accA;
                #pragma unroll
                for (int tap = 0; tap < 9; tap++) {
                    const int di = tap / 3, dj = tap - 3 * di;
                    uint64_t w2 = *(const uint64_t*)&W1d[oc * 9 + tap];
                    fma2(accA, pk[di][dj], w2);
                    fma2(accB, pk[di + 1][dj], w2);
                }
                float a00, a01, a10, a11;
                unpack2(accA, a00, a01);
                unpack2(accB, a10, a11);
                float v = fmaxf(fmaxf(mm00 * fmaxf(a00, 0.f), mm01 * fmaxf(a01, 0.f)),
                                fmaxf(mm10 * fmaxf(a10, 0.f), mm11 * fmaxf(a11, 0.f)));
                uint32_t hu = (uint32_t)__half_as_ushort(__float2half_rn(v));
                if (oc & 1) {
                    hw |= hu << 16;
                    hbuf[lp * 17 + (oc >> 1)] = hw;
                } else hw = hu;
            }
        }
        __syncthreads();
        for (int i = t; i < 8192; i += 256) {
            int px = i >> 4, w = i & 15;
            int oi = half * 16 + (px >> 5), oj = px & 31;
            ghi[((size_t)(b * 34 + oi + 1) * 34 + oj + 1) * 16 + w] = hbuf[px * 17 + w];
        }
        __syncthreads();
    }
}

// ---------------- conv2 via mma.sync fp16 (A hi-only, 256 thr, 2 CTAs/SM) ----------------
#define SM_W     0        // 46080
#define SM_STRIP 46080    // 27200
#define SM_B2    73280    // 256
#define SM_M3    73536    // 1024
#define SM_M4    74560    // 256
#define C2_SMEM  74816

__global__ void __launch_bounds__(256, 2) conv2_mma_kernel(const float* __restrict__ b2) {
    extern __shared__ char sm[];
    float* b2s = (float*)(sm + SM_B2);
    int t = threadIdx.x;
    int b = blockIdx.x >> 1, hf = blockIdx.x & 1;
    int warp = t >> 5, lane = t & 31;
    uint32_t sb = s2u(sm);

    for (int i = t; i < 2880; i += 256)
        *(uint4*)(sm + SM_W + i * 16) = *(const uint4*)(g_w2p + i * 16);
    if (t < 64) b2s[t] = b2[t];
    for (int i = t; i < 1024; i += 256) sm[SM_M3 + i] = (char)g_m3[b * 1024 + i];
    sm[SM_M4 + t] = (char)g_m4[b * 256 + t];

    int wm = warp & 3, wn = warp >> 2;   // 4 M x 2 N(32oc)
    int oc0 = wn * 32;
    int g = lane >> 2, qu = lane & 3;
    int rowlane = lane & 15;
    int aKoff = (lane >= 16) ? 16 : 0;
    int grpB = lane >> 3;
    int ocoffB = ((grpB >> 1) << 3) + (lane & 7);
    int bKoff = (grpB & 1) * 16;

    for (int it = 0; it < 2; it++) {
        int mt = hf * 2 + it;
        __syncthreads();
        const uint4* shp = (const uint4*)g_p1hi + ((size_t)(b * 34 + 8 * mt) * 34) * 4;
        for (int j = t; j < 1360; j += 256) {
            uint4 v = shp[j];
            int px = j >> 2, q = j & 3;
            *(uint4*)(sm + SM_STRIP + px * 80 + q * 16) = v;
        }
        __syncthreads();

        float acc[4][4][4];
        #pragma unroll
        for (int mi = 0; mi < 4; mi++)
            #pragma unroll
            for (int nt = 0; nt < 4; nt++)
                #pragma unroll
                for (int e = 0; e < 4; e++) acc[mi][nt][e] = 0.f;

        #pragma unroll
        for (int tap = 0; tap < 9; tap++) {
            const int di = tap / 3, dj = tap - di * 3;
            #pragma unroll
            for (int kc = 0; kc < 2; kc++) {
                uint32_t ah[4][4];
                #pragma unroll
                for (int mi = 0; mi < 4; mi++) {
                    int lr = 2 * wm + (mi >> 1);
                    int c0 = (mi & 1) * 16;
                    uint32_t addr = sb + SM_STRIP +
                        (uint32_t)(((lr + di) * 34 + c0 + rowlane + dj) * 80 + kc * 32 + aKoff);
                    LDSM4(ah[mi], addr);
                }
                #pragma unroll
                for (int nb = 0; nb < 2; nb++) {
                    uint32_t bh[4];
                    uint32_t baddr = sb + SM_W +
                        (uint32_t)(tap * 5120 + (oc0 + nb * 16 + ocoffB) * 80 + kc * 32 + bKoff);
                    LDSM4(bh, baddr);
                    #pragma unroll
                    for (int mi = 0; mi < 4; mi++)
                        #pragma unroll
                        for (int s2 = 0; s2 < 2; s2++) {
                            int nt = nb * 2 + s2;
                            MMA16816F(acc[mi][nt], ah[mi], bh[s2 * 2], bh[s2 * 2 + 1]);
                        }
                }
            }
        }

        int mtrow = mt * 8;
        int prg = mt * 4 + wm;
        #pragma unroll
        for (int mi = 0; mi < 2; mi++)
            #pragma unroll
            for (int nt = 0; nt < 4; nt++)
                #pragma unroll
                for (int e = 0; e < 4; e++) {
                    int col = mi * 16 + g + ((e >> 1) ? 8 : 0);
                    int occ = oc0 + nt * 8 + qu * 2 + (e & 1);
                    float bb = b2s[occ];
                    float v0 = sm[SM_M3 + (mtrow + 2 * wm) * 32 + col]
                               ? fmaxf(acc[mi][nt][e] + bb, 0.f) : 0.f;
                    float v1 = sm[SM_M3 + (mtrow + 2 * wm + 1) * 32 + col]
                               ? fmaxf(acc[mi + 2][nt][e] + bb, 0.f) : 0.f;
                    float v = fmaxf(v0, v1);
                    float vp = __shfl_xor_sync(0xffffffffu, v, 4);
                    if (!(g & 1)) {
                        float pooled = fmaxf(v, vp);
                        int pc = col >> 1;
                        if (!sm[SM_M4 + prg * 16 + pc]) pooled = 0.f;
                        __half hb = __float2half_rn(pooled);
                        __half lb = __float2half_rn(pooled - __half2float(hb));
                        size_t o = (size_t)b * 16384 + occ * 256 + prg * 16 + pc;
                        g_p2h[o] = hb;
                        g_p2l[o] = lb;
                    }
                }
    }
}

// ---------------- FC1 via mma.sync fp16 (2-term: Ah*Wh + Al*Wh) ----------------
// smem: Ah 18432 | Al 18432 | Wh 18432 = 55296 (pitch 144B)
#define F1_AH 0
#define F1_AL 18432
#define F1_WH 36864
#define F1_SMEM 55296

// grid (2 M-tiles of 128, 128 k-chunks of 128), 256 threads
__global__ void __launch_bounds__(256, 2) fc1_mma_kernel() {
    extern __shared__ char sm[];
    int t = threadIdx.x;
    int mtile = blockIdx.x, kc = blockIdx.y;
    int warp = t >> 5, lane = t & 31;
    uint32_t sb = s2u(sm);
    int wm = warp & 3, wn = warp >> 2;   // 4 M(32px) x 2 N(64oc)
    int g = lane >> 2, qu = lane & 3;
    int rowlane = lane & 15;
    int aKoff = (lane >= 16) ? 16 : 0;
    int grpB = lane >> 3;
    int ocoffB = ((grpB >> 1) << 3) + (lane & 7);
    int bKoff = (grpB & 1) * 16;

    float acc[2][8][4];
    #pragma unroll
    for (int mi = 0; mi < 2; mi++)
        #pragma unroll
        for (int nt = 0; nt < 8; nt++)
            #pragma unroll
            for (int e = 0; e < 4; e++) acc[mi][nt][e] = 0.f;

    const uint32_t* Ahg = (const uint32_t*)g_p2h;
    const uint32_t* Alg = (const uint32_t*)g_p2l;
    const uint32_t* Whg = (const uint32_t*)g_wf1h;

    for (int sub = 0; sub < 2; sub++) {
        int k0 = kc * 128 + sub * 64;
        __syncthreads();
        for (int i = t; i < 4096; i += 256) {
            int row = i >> 5, w = i & 31;
            size_t gi = (size_t)(mtile * 128 + row) * 8192 + (k0 >> 1) + w;
            *(uint32_t*)(sm + F1_AH + row * 144 + w * 4) = Ahg[gi];
            *(uint32_t*)(sm + F1_AL + row * 144 + w * 4) = Alg[gi];
            size_t wi = (size_t)row * 8192 + (k0 >> 1) + w;   // row == oc (128)
            *(uint32_t*)(sm + F1_WH + row * 144 + w * 4) = Whg[wi];
        }
        __syncthreads();
        #pragma unroll
        for (int k16 = 0; k16 < 4; k16++) {
            uint32_t ah[2][4], al[2][4];
            #pragma unroll
            for (int mi = 0; mi < 2; mi++) {
                int row = wm * 32 + mi * 16 + rowlane;
                uint32_t addr = sb + F1_AH + (uint32_t)(row * 144 + k16 * 32 + aKoff);
                LDSM4(ah[mi], addr);
                LDSM4(al[mi], addr + 18432);
            }
            #pragma unroll
            for (int nb = 0; nb < 4; nb++) {
                uint32_t bh[4];
                int oc0 = wn * 64 + nb * 16;
                uint32_t baddr = sb + F1_WH + (uint32_t)((oc0 + ocoffB) * 144 + k16 * 32 + bKoff);
                LDSM4(bh, baddr);
                #pragma unroll
                for (int mi = 0; mi < 2; mi++)
                    #pragma unroll
                    for (int s2 = 0; s2 < 2; s2++) {
                        int nt = nb * 2 + s2;
                        MMA16816F(acc[mi][nt], ah[mi], bh[s2 * 2], bh[s2 * 2 + 1]);
                        MMA16816F(acc[mi][nt], al[mi], bh[s2 * 2], bh[s2 * 2 + 1]);
                    }
            }
        }
    }
    #pragma unroll
    for (int mi = 0; mi < 2; mi++)
        #pragma unroll
        for (int nt = 0; nt < 8; nt++)
            #pragma unroll
            for (int e = 0; e < 4; e++) {
                int row = mtile * 128 + wm * 32 + mi * 16 + g + ((e >> 1) ? 8 : 0);
                int col = wn * 64 + nt * 8 + qu * 2 + (e & 1);
                atomicAdd(&g_h[row * 128 + col], acc[mi][nt][e]);
            }
}

// ---------------- FC2 warp-parallel ----------------
__global__ void __launch_bounds__(320) fc2_kernel(const float* __restrict__ Wfc2,
                                                  const float* __restrict__ bfc2,
                                                  float* __restrict__ out) {
    int b = blockIdx.x;
    int w = threadIdx.x >> 5, lane = threadIdx.x & 31;
    float s = 0.f;
    const float* wp = Wfc2 + w * 128;
    const float* hp = g_h + b * 128;
    #pragma unroll
    for (int k = lane; k < 128; k += 32)
        s += fmaxf(hp[k], 0.f) * wp[k];
    #pragma unroll
    for (int o = 16; o; o >>= 1) s += __shfl_xor_sync(0xffffffffu, s, o);
    if (lane == 0) out[b * 10 + w] = s + bfc2[w];
}

// ---------------- launch ----------------
extern "C" void kernel_launch(void* const* d_in, const int* in_sizes, int n_in,
                              void* d_out, int out_size) {
    const float* x    = (const float*)d_in[0];
    const int*   cmap = (const int*)  d_in[1];
    const float* W1   = (const float*)d_in[2];
    const float* b1   = (const float*)d_in[3];
    const float* W2   = (const float*)d_in[4];
    const float* b2   = (const float*)d_in[5];
    const float* Wfc1 = (const float*)d_in[6];
    const float* bfc1 = (const float*)d_in[7];
    const float* Wfc2 = (const float*)d_in[8];
    const float* bfc2 = (const float*)d_in[9];
    float* out = (float*)d_out;

    cudaFuncSetAttribute(conv1_kernel, cudaFuncAttributeMaxDynamicSharedMemorySize, C1_SMEM);
    cudaFuncSetAttribute(conv2_mma_kernel, cudaFuncAttributeMaxDynamicSharedMemorySize, C2_SMEM);
    cudaFuncSetAttribute(fc1_mma_kernel, cudaFuncAttributeMaxDynamicSharedMemorySize, F1_SMEM);

    conv1_kernel<<<BATCH, 256, C1_SMEM>>>(x, cmap, W1, b1, bfc1, Wfc1, W2);
    conv2_mma_kernel<<<BATCH * 2, 256, C2_SMEM>>>(b2);
    dim3 g1(2, 128);
    fc1_mma_kernel<<<g1, 256, F1_SMEM>>>();
    fc2_kernel<<<BATCH, 320>>>(Wfc2, bfc2, out);
}

// round 16
// speedup vs baseline: 1.9956x; 1.0255x over previous
#include <cuda_runtime.h>
#include <cuda_fp16.h>
#include <cstdint>

#define BATCH 256

// ---------------- scratch ----------------
__device__ unsigned char g_m3[BATCH * 1024];
__device__ unsigned char g_m4[BATCH * 256];
__device__ __align__(16) __half g_p1hi[BATCH * 34 * 34 * 32];
__device__ __align__(16) __half g_p2h[BATCH * 16384];
__device__ __align__(16) __half g_p2l[BATCH * 16384];
__device__ __align__(16) __half g_wf1h[128 * 16384];
__device__ __align__(16) unsigned char g_w2p[46080];   // conv2 smem-layout W image
__device__ float g_h[BATCH * 128];

// ---------------- helpers ----------------
static __device__ __forceinline__ uint32_t s2u(const void* p) {
    uint32_t a;
    asm("{ .reg .u64 t; cvta.to.shared.u64 t, %1; cvt.u32.u64 %0, t; }" : "=r"(a) : "l"(p));
    return a;
}
#define LDSM4(r, addr) \
    asm volatile("ldmatrix.sync.aligned.m8n8.x4.shared.b16 {%0,%1,%2,%3}, [%4];" \
        : "=r"((r)[0]), "=r"((r)[1]), "=r"((r)[2]), "=r"((r)[3]) : "r"(addr))
#define MMA16816F(c, a, b0, b1) \
    asm volatile("mma.sync.aligned.m16n8k16.row.col.f32.f16.f16.f32 " \
        "{%0,%1,%2,%3}, {%4,%5,%6,%7}, {%8,%9}, {%0,%1,%2,%3};" \
        : "+f"((c)[0]), "+f"((c)[1]), "+f"((c)[2]), "+f"((c)[3]) \
        : "r"((a)[0]), "r"((a)[1]), "r"((a)[2]), "r"((a)[3]), "r"(b0), "r"(b1))
#define CPA16(smem, gptr) \
    asm volatile("cp.async.cg.shared.global [%0], [%1], 16;" :: "r"(smem), "l"(gptr) : "memory")
#define CPA_COMMIT() asm volatile("cp.async.commit_group;" ::: "memory")
#define CPA_WAIT(n)  asm volatile("cp.async.wait_group %0;" :: "n"(n) : "memory")

static __device__ __forceinline__ uint64_t pack2(float lo, float hi) {
    uint64_t d;
    asm("mov.b64 %0, {%1, %2};" : "=l"(d) : "f"(lo), "f"(hi));
    return d;
}
static __device__ __forceinline__ void fma2(uint64_t& d, uint64_t a, uint64_t b) {
    asm("fma.rn.f32x2 %0, %1, %2, %0;" : "+l"(d) : "l"(a), "l"(b));
}
static __device__ __forceinline__ void unpack2(uint64_t v, float& lo, float& hi) {
    asm("mov.b64 {%0, %1}, %2;" : "=f"(lo), "=f"(hi) : "l"(v));
}

// ---------------- conv1 fused: w-preps + masks + conv + pool + border + h-init ----------------
#define C1_XS    0        // 64*65*4 = 16640
#define C1_W1D   16640    // 288 float2 = 2304
#define C1_B1    18944    // 128
#define C1_CS    19072    // 4096
#define C1_M1    23168    // 4096
#define C1_M2    27264    // 1024
#define C1_M3    28288    // 1024
#define C1_M4    29312    // 256
#define C1_HBUF  29568    // 512*17*4 = 34816
#define C1_SMEM  64384

__global__ void __launch_bounds__(256, 2) conv1_kernel(const float* __restrict__ x,
                                                       const int* __restrict__ cmap,
                                                       const float* __restrict__ W1,
                                                       const float* __restrict__ b1,
                                                       const float* __restrict__ bfc1,
                                                       const float* __restrict__ Wfc1,
                                                       const float* __restrict__ W2) {
    extern __shared__ char sm1[];
    float* xs = (float*)(sm1 + C1_XS);                 // pitch 65
    float2* W1d = (float2*)(sm1 + C1_W1D);
    float* b1s = (float*)(sm1 + C1_B1);
    unsigned char* cs  = (unsigned char*)(sm1 + C1_CS);
    unsigned char* m1s = (unsigned char*)(sm1 + C1_M1);
    unsigned char* m2s = (unsigned char*)(sm1 + C1_M2);
    unsigned char* m3s = (unsigned char*)(sm1 + C1_M3);
    unsigned char* m4s = (unsigned char*)(sm1 + C1_M4);
    uint32_t* hbuf = (uint32_t*)(sm1 + C1_HBUF);       // [512][17]
    int b = blockIdx.x, t = threadIdx.x;

    // distributed Wfc1 -> fp16 hi (8192 floats per CTA)
    {
        const float4* src = (const float4*)Wfc1 + (size_t)b * 2048;
        __half2* dst = (__half2*)(g_wf1h + (size_t)b * 8192);
        for (int i = t; i < 2048; i += 256) {
            float4 v = src[i];
            __half2 h0, h1;
            h0.x = __float2half_rn(v.x); h0.y = __float2half_rn(v.y);
            h1.x = __float2half_rn(v.z); h1.y = __float2half_rn(v.w);
            dst[i * 2] = h0;
            dst[i * 2 + 1] = h1;
        }
    }
    // distributed W2 -> conv2 smem-layout image (72 weights per CTA)
    if (t < 72) {
        int i = b * 72 + t;
        int oc = i / 288, rem = i - oc * 288, ic = rem / 9, tap = rem - ic * 9;
        *(__half*)(g_w2p + tap * 5120 + oc * 80 + ic * 2) = __float2half_rn(W2[i]);
    }

    const float* xb = x + b * 4096;
    const int* cb = cmap + b * 4096;
    for (int i = t; i < 4096; i += 256) {
        xs[(i >> 6) * 65 + (i & 63)] = xb[i];
        cs[i] = (unsigned char)cb[i];
    }
    for (int i = t; i < 288; i += 256) { float w = W1[i]; W1d[i] = make_float2(w, w); }
    if (t < 32) b1s[t] = b1[t];
    if (t < 128) g_h[b * 128 + t] = bfc1[t];
    __syncthreads();

    for (int p = t; p < 4096; p += 256) {
        int i = p >> 6, j = p & 63;
        int s = 0;
        for (int di = 0; di < 3; di++) {
            int ii = i + di; if (ii >= 64) break;
            for (int dj = 0; dj < 3; dj++) {
                int jj = j + dj; if (jj >= 64) break;
                s += cs[(ii << 6) | jj];
            }
        }
        m1s[p] = (s > 1);
    }
    __syncthreads();
    for (int p = t; p < 1024; p += 256) {
        int i = p >> 5, j = p & 31;
        int s = m1s[((2 * i) << 6) | (2 * j)] + m1s[((2 * i) << 6) | (2 * j + 1)]
              + m1s[((2 * i + 1) << 6) | (2 * j)] + m1s[((2 * i + 1) << 6) | (2 * j + 1)];
        m2s[p] = (s > 1);
    }
    __syncthreads();
    for (int p = t; p < 1024; p += 256) {
        int i = p >> 5, j = p & 31;
        int s = 0;
        for (int di = 0; di < 3; di++) {
            int ii = i + di; if (ii >= 32) break;
            for (int dj = 0; dj < 3; dj++) {
                int jj = j + dj; if (jj >= 32) break;
                s += m2s[(ii << 5) | jj];
            }
        }
        m3s[p] = (s > 1);
    }
    __syncthreads();
    for (int p = t; p < 1024; p += 256) g_m3[b * 1024 + p] = m3s[p];
    if (t < 256) {
        int i = t >> 4, j = t & 15;
        int s = m3s[((2 * i) << 5) | (2 * j)] + m3s[((2 * i) << 5) | (2 * j + 1)]
              + m3s[((2 * i + 1) << 5) | (2 * j)] + m3s[((2 * i + 1) << 5) | (2 * j + 1)];
        m4s[t] = (s > 1);
        g_m4[b * 256 + t] = m4s[t];
    }

    // p1 border zero
    {
        const uint4 z = {0u, 0u, 0u, 0u};
        for (int i = t; i < 528; i += 256) {
            int q = i & 3, cl = i >> 2;
            int row, col;
            if (cl < 34)       { row = 0;        col = cl; }
            else if (cl < 68)  { row = 33;       col = cl - 34; }
            else if (cl < 100) { row = cl - 67;  col = 0; }
            else               { row = cl - 99;  col = 33; }
            ((uint4*)g_p1hi)[((size_t)(b * 34 + row) * 34 + col) * 4 + q] = z;
        }
    }

    uint32_t* ghi = (uint32_t*)g_p1hi;

    for (int half = 0; half < 2; half++) {
        #pragma unroll
        for (int pp = 0; pp < 2; pp++) {
            int lp = pp * 256 + t;
            int p  = half * 512 + lp;
            int oi = p >> 5, oj = p & 31;
            if (!m2s[p]) {
                #pragma unroll
                for (int k = 0; k < 16; k++) hbuf[lp * 17 + k] = 0u;
                continue;
            }
            float xv[4][4];
            int r0 = 2 * oi - 1, c0 = 2 * oj - 1;
            #pragma unroll
            for (int a = 0; a < 4; a++) {
                int r = r0 + a;
                #pragma unroll
                for (int c = 0; c < 4; c++) {
                    int cc = c0 + c;
                    xv[a][c] = (r >= 0 && r < 64 && cc >= 0 && cc < 64) ? xs[r * 65 + cc] : 0.f;
                }
            }
            uint64_t pk[4][3];
            #pragma unroll
            for (int r = 0; r < 4; r++)
                #pragma unroll
                for (int dj = 0; dj < 3; dj++)
                    pk[r][dj] = pack2(xv[r][dj], xv[r][dj + 1]);
            float mm00 = m1s[((2 * oi) << 6) | (2 * oj)]     ? 1.f : 0.f;
            float mm01 = m1s[((2 * oi) << 6) | (2 * oj + 1)] ? 1.f : 0.f;
            float mm10 = m1s[((2 * oi + 1) << 6) | (2 * oj)] ? 1.f : 0.f;
            float mm11 = m1s[((2 * oi + 1) << 6) | (2 * oj + 1)] ? 1.f : 0.f;
            uint32_t hw = 0;
            for (int oc = 0; oc < 32; oc++) {
                float bb = b1s[oc];
                uint64_t accA = pack2(bb, bb);
                uint64_t accB = accA;
                #pragma unroll
                for (int tap = 0; tap < 9; tap++) {
                    const int di = tap / 3, dj = tap - 3 * di;
                    uint64_t w2 = *(const uint64_t*)&W1d[oc * 9 + tap];
                    fma2(accA, pk[di][dj], w2);
                    fma2(accB, pk[di + 1][dj], w2);
                }
                float a00, a01, a10, a11;
                unpack2(accA, a00, a01);
                unpack2(accB, a10, a11);
                float v = fmaxf(fmaxf(mm00 * fmaxf(a00, 0.f), mm01 * fmaxf(a01, 0.f)),
                                fmaxf(mm10 * fmaxf(a10, 0.f), mm11 * fmaxf(a11, 0.f)));
                uint32_t hu = (uint32_t)__half_as_ushort(__float2half_rn(v));
                if (oc & 1) {
                    hw |= hu << 16;
                    hbuf[lp * 17 + (oc >> 1)] = hw;
                } else hw = hu;
            }
        }
        __syncthreads();
        for (int i = t; i < 8192; i += 256) {
            int px = i >> 4, w = i & 15;
            int oi = half * 16 + (px >> 5), oj = px & 31;
            ghi[((size_t)(b * 34 + oi + 1) * 34 + oj + 1) * 16 + w] = hbuf[px * 17 + w];
        }
        __syncthreads();
    }
}

// ---------------- conv2: mma.sync fp16, cp.async double-buffered strip ----------------
#define SM_W     0        // 46080
#define SM_S0    46080    // 27200
#define SM_S1    73280    // 27200
#define SM_B2    100480   // 256
#define SM_M3    100736   // 1024
#define SM_M4    101760   // 256
#define C2_SMEM  102016

__global__ void __launch_bounds__(256, 2) conv2_mma_kernel(const float* __restrict__ b2) {
    extern __shared__ char sm[];
    float* b2s = (float*)(sm + SM_B2);
    int t = threadIdx.x;
    int b = blockIdx.x >> 1, hf = blockIdx.x & 1;
    int warp = t >> 5, lane = t & 31;
    uint32_t sb = s2u(sm);

    // group A: W image + strip0
    for (int i = t; i < 2880; i += 256)
        CPA16(sb + SM_W + i * 16, (const char*)g_w2p + i * 16);
    {
        const uint4* shp = (const uint4*)g_p1hi + ((size_t)(b * 34 + 8 * (hf * 2)) * 34) * 4;
        for (int j = t; j < 1360; j += 256) {
            int px = j >> 2, q = j & 3;
            CPA16(sb + SM_S0 + px * 80 + q * 16, shp + j);
        }
    }
    CPA_COMMIT();
    // group B: strip1
    {
        const uint4* shp = (const uint4*)g_p1hi + ((size_t)(b * 34 + 8 * (hf * 2 + 1)) * 34) * 4;
        for (int j = t; j < 1360; j += 256) {
            int px = j >> 2, q = j & 3;
            CPA16(sb + SM_S1 + px * 80 + q * 16, shp + j);
        }
    }
    CPA_COMMIT();

    if (t < 64) b2s[t] = b2[t];
    for (int i = t; i < 1024; i += 256) sm[SM_M3 + i] = (char)g_m3[b * 1024 + i];
    sm[SM_M4 + t] = (char)g_m4[b * 256 + t];

    int wm = warp & 3, wn = warp >> 2;   // 4 M x 2 N(32oc)
    int oc0 = wn * 32;
    int g = lane >> 2, qu = lane & 3;
    int rowlane = lane & 15;
    int aKoff = (lane >= 16) ? 16 : 0;
    int grpB = lane >> 3;
    int ocoffB = ((grpB >> 1) << 3) + (lane & 7);
    int bKoff = (grpB & 1) * 16;

    CPA_WAIT(1);
    __syncthreads();

    for (int it = 0; it < 2; it++) {
        int mt = hf * 2 + it;
        uint32_t strip = sb + (it ? SM_S1 : SM_S0);

        float acc[4][4][4];
        #pragma unroll
        for (int mi = 0; mi < 4; mi++)
            #pragma unroll
            for (int nt = 0; nt < 4; nt++)
                #pragma unroll
                for (int e = 0; e < 4; e++) acc[mi][nt][e] = 0.f;

        #pragma unroll
        for (int tap = 0; tap < 9; tap++) {
            const int di = tap / 3, dj = tap - di * 3;
            #pragma unroll
            for (int kc = 0; kc < 2; kc++) {
                uint32_t ah[4][4];
                #pragma unroll
                for (int mi = 0; mi < 4; mi++) {
                    int lr = 2 * wm + (mi >> 1);
                    int c0 = (mi & 1) * 16;
                    uint32_t addr = strip +
                        (uint32_t)(((lr + di) * 34 + c0 + rowlane + dj) * 80 + kc * 32 + aKoff);
                    LDSM4(ah[mi], addr);
                }
                #pragma unroll
                for (int nb = 0; nb < 2; nb++) {
                    uint32_t bh[4];
                    uint32_t baddr = sb + SM_W +
                        (uint32_t)(tap * 5120 + (oc0 + nb * 16 + ocoffB) * 80 + kc * 32 + bKoff);
                    LDSM4(bh, baddr);
                    #pragma unroll
                    for (int mi = 0; mi < 4; mi++)
                        #pragma unroll
                        for (int s2 = 0; s2 < 2; s2++) {
                            int nt = nb * 2 + s2;
                            MMA16816F(acc[mi][nt], ah[mi], bh[s2 * 2], bh[s2 * 2 + 1]);
                        }
                }
            }
        }

        int mtrow = mt * 8;
        int prg = mt * 4 + wm;
        #pragma unroll
        for (int mi = 0; mi < 2; mi++)
            #pragma unroll
            for (int nt = 0; nt < 4; nt++)
                #pragma unroll
                for (int e = 0; e < 4; e++) {
                    int col = mi * 16 + g + ((e >> 1) ? 8 : 0);
                    int occ = oc0 + nt * 8 + qu * 2 + (e & 1);
                    float bb = b2s[occ];
                    float v0 = sm[SM_M3 + (mtrow + 2 * wm) * 32 + col]
                               ? fmaxf(acc[mi][nt][e] + bb, 0.f) : 0.f;
                    float v1 = sm[SM_M3 + (mtrow + 2 * wm + 1) * 32 + col]
                               ? fmaxf(acc[mi + 2][nt][e] + bb, 0.f) : 0.f;
                    float v = fmaxf(v0, v1);
                    float vp = __shfl_xor_sync(0xffffffffu, v, 4);
                    if (!(g & 1)) {
                        float pooled = fmaxf(v, vp);
                        int pc = col >> 1;
                        if (!sm[SM_M4 + prg * 16 + pc]) pooled = 0.f;
                        __half hb = __float2half_rn(pooled);
                        __half lb = __float2half_rn(pooled - __half2float(hb));
                        size_t o = (size_t)b * 16384 + occ * 256 + prg * 16 + pc;
                        g_p2h[o] = hb;
                        g_p2l[o] = lb;
                    }
                }
        if (it == 0) {
            CPA_WAIT(0);
            __syncthreads();
        }
    }
}

// ---------------- FC1: mma.sync fp16 (2-term), cp.async double-buffered subs ----------------
// per-sub buffers: Ah 18432 | Al 18432 | Wh 18432 = 55296; x2 = 110592 (pitch 144B)
#define F1_AH 0
#define F1_AL 18432
#define F1_WH 36864
#define F1_BUF 55296
#define F1_SMEM 110592

// grid (2 M-tiles of 128, 128 k-chunks of 128), 256 threads
__global__ void __launch_bounds__(256, 2) fc1_mma_kernel() {
    extern __shared__ char sm[];
    int t = threadIdx.x;
    int mtile = blockIdx.x, kc = blockIdx.y;
    int warp = t >> 5, lane = t & 31;
    uint32_t sb = s2u(sm);
    int wm = warp & 3, wn = warp >> 2;   // 4 M(32px) x 2 N(64oc)
    int g = lane >> 2, qu = lane & 3;
    int rowlane = lane & 15;
    int aKoff = (lane >= 16) ? 16 : 0;
    int grpB = lane >> 3;
    int ocoffB = ((grpB >> 1) << 3) + (lane & 7);
    int bKoff = (grpB & 1) * 16;

    const uint4* Ahg = (const uint4*)g_p2h;
    const uint4* Alg = (const uint4*)g_p2l;
    const uint4* Whg = (const uint4*)g_wf1h;

    // stage both subs via cp.async (groups A and B)
    #pragma unroll
    for (int sub = 0; sub < 2; sub++) {
        uint32_t base = sb + sub * F1_BUF;
        int kq = kc * 16 + sub * 8;     // uint4 offset within 2048-uint4 row
        for (int i = t; i < 1024; i += 256) {
            int row = i >> 3, q = i & 7;
            size_t ga = (size_t)(mtile * 128 + row) * 2048 + kq + q;
            size_t gw = (size_t)row * 2048 + kq + q;   // row == oc
            CPA16(base + F1_AH + row * 144 + q * 16, Ahg + ga);
            CPA16(base + F1_AL + row * 144 + q * 16, Alg + ga);
            CPA16(base + F1_WH + row * 144 + q * 16, Whg + gw);
        }
        CPA_COMMIT();
    }

    float acc[2][8][4];
    #pragma unroll
    for (int mi = 0; mi < 2; mi++)
        #pragma unroll
        for (int nt = 0; nt < 8; nt++)
            #pragma unroll
            for (int e = 0; e < 4; e++) acc[mi][nt][e] = 0.f;

    CPA_WAIT(1);
    __syncthreads();

    #pragma unroll
    for (int sub = 0; sub < 2; sub++) {
        uint32_t base = sb + sub * F1_BUF;
        #pragma unroll
        for (int k16 = 0; k16 < 4; k16++) {
            uint32_t ah[2][4], al[2][4];
            #pragma unroll
            for (int mi = 0; mi < 2; mi++) {
                int row = wm * 32 + mi * 16 + rowlane;
                uint32_t addr = base + F1_AH + (uint32_t)(row * 144 + k16 * 32 + aKoff);
                LDSM4(ah[mi], addr);
                LDSM4(al[mi], addr + 18432);
            }
            #pragma unroll
            for (int nb = 0; nb < 4; nb++) {
                uint32_t bh[4];
                int oc0 = wn * 64 + nb * 16;
                uint32_t baddr = base + F1_WH + (uint32_t)((oc0 + ocoffB) * 144 + k16 * 32 + bKoff);
                LDSM4(bh, baddr);
                #pragma unroll
                for (int mi = 0; mi < 2; mi++)
                    #pragma unroll
                    for (int s2 = 0; s2 < 2; s2++) {
                        int nt = nb * 2 + s2;
                        MMA16816F(acc[mi][nt], ah[mi], bh[s2 * 2], bh[s2 * 2 + 1]);
                        MMA16816F(acc[mi][nt], al[mi], bh[s2 * 2], bh[s2 * 2 + 1]);
                    }
            }
        }
        if (sub == 0) {
            CPA_WAIT(0);
            __syncthreads();
        }
    }
    #pragma unroll
    for (int mi = 0; mi < 2; mi++)
        #pragma unroll
        for (int nt = 0; nt < 8; nt++)
            #pragma unroll
            for (int e = 0; e < 4; e++) {
                int row = mtile * 128 + wm * 32 + mi * 16 + g + ((e >> 1) ? 8 : 0);
                int col = wn * 64 + nt * 8 + qu * 2 + (e & 1);
                atomicAdd(&g_h[row * 128 + col], acc[mi][nt][e]);
            }
}

// ---------------- FC2 warp-parallel ----------------
__global__ void __launch_bounds__(320) fc2_kernel(const float* __restrict__ Wfc2,
                                                  const float* __restrict__ bfc2,
                                                  float* __restrict__ out) {
    int b = blockIdx.x;
    int w = threadIdx.x >> 5, lane = threadIdx.x & 31;
    float s = 0.f;
    const float* wp = Wfc2 + w * 128;
    const float* hp = g_h + b * 128;
    #pragma unroll
    for (int k = lane; k < 128; k += 32)
        s += fmaxf(hp[k], 0.f) * wp[k];
    #pragma unroll
    for (int o = 16; o; o >>= 1) s += __shfl_xor_sync(0xffffffffu, s, o);
    if (lane == 0) out[b * 10 + w] = s + bfc2[w];
}

// ---------------- launch ----------------
extern "C" void kernel_launch(void* const* d_in, const int* in_sizes, int n_in,
                              void* d_out, int out_size) {
    const float* x    = (const float*)d_in[0];
    const int*   cmap = (const int*)  d_in[1];
    const float* W1   = (const float*)d_in[2];
    const float* b1   = (const float*)d_in[3];
    const float* W2   = (const float*)d_in[4];
    const float* b2   = (const float*)d_in[5];
    const float* Wfc1 = (const float*)d_in[6];
    const float* bfc1 = (const float*)d_in[7];
    const float* Wfc2 = (const float*)d_in[8];
    const float* bfc2 = (const float*)d_in[9];
    float* out = (float*)d_out;

    cudaFuncSetAttribute(conv1_kernel, cudaFuncAttributeMaxDynamicSharedMemorySize, C1_SMEM);
    cudaFuncSetAttribute(conv2_mma_kernel, cudaFuncAttributeMaxDynamicSharedMemorySize, C2_SMEM);
    cudaFuncSetAttribute(fc1_mma_kernel, cudaFuncAttributeMaxDynamicSharedMemorySize, F1_SMEM);

    conv1_kernel<<<BATCH, 256, C1_SMEM>>>(x, cmap, W1, b1, bfc1, Wfc1, W2);
    conv2_mma_kernel<<<BATCH * 2, 256, C2_SMEM>>>(b2);
    dim3 g1(2, 128);
    fc1_mma_kernel<<<g1, 256, F1_SMEM>>>();
    fc2_kernel<<<BATCH, 320>>>(Wfc2, bfc2, out);
}